// round 5
// baseline (speedup 1.0000x reference)
#include <cuda_runtime.h>
#include <cuda_bf16.h>
#include <stdint.h>
#include <stddef.h>

namespace {
constexpr int kC       = 64;
constexpr int kN       = 512 * 512;     // 262144
constexpr int kChunk   = 128;
constexpr int kNChunks = kN / kChunk;   // 2048
constexpr int kGrid1   = 296;           // syrk blocks (even: 2 batches interleaved)
constexpr int kBPB     = kGrid1 / 2;    // 148 blocks per batch
constexpr int kP1      = 136;           // bf16 smem pitch (conflict-free)
constexpr int kPF      = 132;           // f32 smem pitch
constexpr int kPM      = 72;            // bf16 M pitch (conflict-free)
}

__device__ float g_part[kGrid1][kC][kC];
__device__ __nv_bfloat16 g_M[2][kC][kC];

__device__ __forceinline__ void mma_bf16(float c[4], const uint32_t a[4],
                                         const uint32_t b[2]) {
    asm volatile(
        "mma.sync.aligned.m16n8k16.row.col.f32.bf16.bf16.f32 "
        "{%0,%1,%2,%3}, {%4,%5,%6,%7}, {%8,%9}, {%0,%1,%2,%3};\n"
        : "+f"(c[0]), "+f"(c[1]), "+f"(c[2]), "+f"(c[3])
        : "r"(a[0]), "r"(a[1]), "r"(a[2]), "r"(a[3]), "r"(b[0]), "r"(b[1]));
}

__device__ __forceinline__ uint32_t ld_u32_bf(const __nv_bfloat16* p) {
    return *reinterpret_cast<const uint32_t*>(p);
}

__device__ __forceinline__ uint32_t pack_bf16x2(float lo, float hi) {
    __nv_bfloat162 h = __floats2bfloat162_rn(lo, hi);
    return *reinterpret_cast<uint32_t*>(&h);
}

// ------------------------------------------------------------------ pass 1
// Xcov partials: bf16 hi/lo split syrk. Per-warp: two 16x16 C tiles.
__global__ __launch_bounds__(256) void syrk_kernel(const float* __restrict__ x) {
    __shared__ __nv_bfloat16 sH[kC][kP1];
    __shared__ __nv_bfloat16 sL[kC][kP1];

    const int tid = threadIdx.x;
    const int warp = tid >> 5, lane = tid & 31;
    const int g = lane >> 2, t2 = (lane & 3) << 1;
    const int b = blockIdx.x & 1;
    const float* xb = x + (size_t)b * kC * kN;
    const int i0 = warp >> 2, j0 = warp & 3;   // C tile coords

    float acc[2][2][4];
#pragma unroll
    for (int s = 0; s < 2; s++)
#pragma unroll
        for (int n = 0; n < 2; n++)
#pragma unroll
            for (int r = 0; r < 4; r++) acc[s][n][r] = 0.f;

    float4 buf[8];
    int c = blockIdx.x >> 1;
    {
        const int col0 = c * kChunk;
#pragma unroll
        for (int i = 0; i < 8; i++) {
            const int idx4 = tid + (i << 8);
            buf[i] = *reinterpret_cast<const float4*>(
                xb + (size_t)(idx4 >> 5) * kN + col0 + ((idx4 & 31) << 2));
        }
    }

    for (; c < kNChunks; c += kBPB) {
#pragma unroll
        for (int i = 0; i < 8; i++) {
            const int idx4 = tid + (i << 8);
            const int ch = idx4 >> 5, cc = (idx4 & 31) << 2;
            float v[4] = {buf[i].x, buf[i].y, buf[i].z, buf[i].w};
            __nv_bfloat16 h[4], l[4];
#pragma unroll
            for (int k = 0; k < 4; k++) {
                h[k] = __float2bfloat16(v[k]);
                l[k] = __float2bfloat16(v[k] - __bfloat162float(h[k]));
            }
            *reinterpret_cast<__nv_bfloat162*>(&sH[ch][cc])     = __halves2bfloat162(h[0], h[1]);
            *reinterpret_cast<__nv_bfloat162*>(&sH[ch][cc + 2]) = __halves2bfloat162(h[2], h[3]);
            *reinterpret_cast<__nv_bfloat162*>(&sL[ch][cc])     = __halves2bfloat162(l[0], l[1]);
            *reinterpret_cast<__nv_bfloat162*>(&sL[ch][cc + 2]) = __halves2bfloat162(l[2], l[3]);
        }
        __syncthreads();

        const int nc = c + kBPB;                 // prefetch next chunk
        if (nc < kNChunks) {
            const int col0 = nc * kChunk;
#pragma unroll
            for (int i = 0; i < 8; i++) {
                const int idx4 = tid + (i << 8);
                buf[i] = *reinterpret_cast<const float4*>(
                    xb + (size_t)(idx4 >> 5) * kN + col0 + ((idx4 & 31) << 2));
            }
        }

#pragma unroll
        for (int ks = 0; ks < 8; ks++) {
            const int kc = (ks << 4) + t2;
#pragma unroll
            for (int s = 0; s < 2; s++) {
                const int ra = ((i0 + (s << 1)) << 4) + g;
                uint32_t aH[4], aL[4];
                aH[0] = ld_u32_bf(&sH[ra][kc]);     aH[1] = ld_u32_bf(&sH[ra + 8][kc]);
                aH[2] = ld_u32_bf(&sH[ra][kc + 8]); aH[3] = ld_u32_bf(&sH[ra + 8][kc + 8]);
                aL[0] = ld_u32_bf(&sL[ra][kc]);     aL[1] = ld_u32_bf(&sL[ra + 8][kc]);
                aL[2] = ld_u32_bf(&sL[ra][kc + 8]); aL[3] = ld_u32_bf(&sL[ra + 8][kc + 8]);
#pragma unroll
                for (int nh = 0; nh < 2; nh++) {
                    const int rb = (j0 << 4) + (nh << 3) + g;
                    uint32_t bH[2], bL[2];
                    bH[0] = ld_u32_bf(&sH[rb][kc]); bH[1] = ld_u32_bf(&sH[rb][kc + 8]);
                    bL[0] = ld_u32_bf(&sL[rb][kc]); bL[1] = ld_u32_bf(&sL[rb][kc + 8]);
                    mma_bf16(acc[s][nh], aH, bH);
                    mma_bf16(acc[s][nh], aH, bL);
                    mma_bf16(acc[s][nh], aL, bH);
                }
            }
        }
        __syncthreads();
    }

#pragma unroll
    for (int s = 0; s < 2; s++) {
        const int r0 = ((i0 + (s << 1)) << 4) + g;
#pragma unroll
        for (int nh = 0; nh < 2; nh++) {
            const int cb = (j0 << 4) + (nh << 3) + t2;
            g_part[blockIdx.x][r0][cb]         = acc[s][nh][0];
            g_part[blockIdx.x][r0][cb + 1]     = acc[s][nh][1];
            g_part[blockIdx.x][r0 + 8][cb]     = acc[s][nh][2];
            g_part[blockIdx.x][r0 + 8][cb + 1] = acc[s][nh][3];
        }
    }
}

// ------------------------------------------------------------------ pass 2
// Reduce partials -> Xcov; norms, per-head softmax, M = Wp * A * Wv.
__global__ __launch_bounds__(256) void attn_kernel(
    const float* __restrict__ Wq, const float* __restrict__ Wk,
    const float* __restrict__ Wv, const float* __restrict__ Wp,
    const float* __restrict__ rescale)
{
    __shared__ float sXc[kC][kC + 1];
    __shared__ float sT[kC][kC + 1];
    __shared__ float sAttn[kC][16];
    __shared__ float sSq[kC], sSk[kC];

    const int b = blockIdx.x, tid = threadIdx.x;

    for (int idx = tid; idx < kC * kC; idx += 256) {   // fixed-order reduce
        const int r = idx >> 6, cc = idx & 63;
        float s = 0.f;
        for (int gb = b; gb < kGrid1; gb += 2) s += g_part[gb][r][cc];
        sXc[r][cc] = s;
    }
    __syncthreads();

    for (int idx = tid; idx < kC * kC; idx += 256) {   // Tq = Wq * Xc
        const int r = idx >> 6, m = idx & 63;
        float s = 0.f;
#pragma unroll 8
        for (int j = 0; j < 64; j++) s += __ldg(&Wq[(r << 6) + j]) * sXc[j][m];
        sT[r][m] = s;
    }
    __syncthreads();

    if (tid < 64) {                                    // ||q_c||
        float s = 0.f;
        for (int m = 0; m < 64; m++) s += sT[tid][m] * __ldg(&Wq[(tid << 6) + m]);
        sSq[tid] = fmaxf(sqrtf(fmaxf(s, 0.f)), 1e-12f);
    }
    __syncthreads();

    for (int idx = tid; idx < 1024; idx += 256) {      // per-head G = Wk Xc Wq^T
        const int h = idx >> 8, d = (idx >> 4) & 15, e = idx & 15;
        const int kc = (h << 4) + d, qc = (h << 4) + e;
        float s = 0.f;
#pragma unroll 8
        for (int m = 0; m < 64; m++) s += __ldg(&Wk[(kc << 6) + m]) * sT[qc][m];
        sAttn[kc][e] = s;
    }
    __syncthreads();

    for (int idx = tid; idx < kC * kC; idx += 256) {   // Tk = Wk * Xc
        const int r = idx >> 6, m = idx & 63;
        float s = 0.f;
#pragma unroll 8
        for (int j = 0; j < 64; j++) s += __ldg(&Wk[(r << 6) + j]) * sXc[j][m];
        sT[r][m] = s;
    }
    __syncthreads();

    if (tid < 64) {                                    // ||k_c||
        float s = 0.f;
        for (int m = 0; m < 64; m++) s += sT[tid][m] * __ldg(&Wk[(tid << 6) + m]);
        sSk[tid] = fmaxf(sqrtf(fmaxf(s, 0.f)), 1e-12f);
    }
    __syncthreads();

    if (tid < 64) {                                    // rescale + softmax(e)
        const int kc = tid, h = kc >> 4;
        const float rs = __ldg(&rescale[h]);
        const float invk = 1.f / sSk[kc];
        float logit[16], mx = -1e30f;
#pragma unroll
        for (int e = 0; e < 16; e++) {
            logit[e] = sAttn[kc][e] * invk / sSq[(kc & 48) + e] * rs;
            mx = fmaxf(mx, logit[e]);
        }
        float sum = 0.f;
#pragma unroll
        for (int e = 0; e < 16; e++) { logit[e] = expf(logit[e] - mx); sum += logit[e]; }
        const float inv = 1.f / sum;
#pragma unroll
        for (int e = 0; e < 16; e++) sAttn[kc][e] = logit[e] * inv;
    }
    __syncthreads();

    for (int idx = tid; idx < kC * kC; idx += 256) {   // R = A_blockdiag * Wv
        const int r = idx >> 6, cc = idx & 63, h = r >> 4;
        float s = 0.f;
#pragma unroll
        for (int e = 0; e < 16; e++)
            s += sAttn[r][e] * __ldg(&Wv[(((h << 4) + e) << 6) + cc]);
        sXc[r][cc] = s;
    }
    __syncthreads();

    for (int idx = tid; idx < kC * kC; idx += 256) {   // M = Wp * R -> bf16
        const int o = idx >> 6, cc = idx & 63;
        float s = 0.f;
#pragma unroll 8
        for (int j = 0; j < 64; j++) s += __ldg(&Wp[(o << 6) + j]) * sXc[j][cc];
        g_M[b][o][cc] = __float2bfloat16(s);
    }
}

// ------------------------------------------------------------------ pass 3
// out = x + M x + bp.  One 64x128 chunk per block; residual fp32, Mx via mma.
__global__ __launch_bounds__(256) void apply_kernel(
    const float* __restrict__ x, const float* __restrict__ bp,
    float* __restrict__ out)
{
    __shared__ float sXf[kC][kPF];
    __shared__ __nv_bfloat16 sM[kC][kPM];

    const int tid = threadIdx.x;
    const int warp = tid >> 5, lane = tid & 31;
    const int g = lane >> 2, t2 = (lane & 3) << 1;
    const int gid = blockIdx.x;
    const int b = gid >> 11;
    const int col0 = (gid & 2047) * kChunk;
    const float* xb = x + (size_t)b * kC * kN;
    float* ob = out + (size_t)b * kC * kN;

    for (int idx = tid; idx < kC * kC; idx += 256)
        sM[idx >> 6][idx & 63] = g_M[b][idx >> 6][idx & 63];

#pragma unroll
    for (int i = 0; i < 8; i++) {
        const int idx4 = tid + (i << 8);
        const int ch = idx4 >> 5, c4 = idx4 & 31;
        *reinterpret_cast<float4*>(&sXf[ch][c4 << 2]) =
            *reinterpret_cast<const float4*>(xb + (size_t)ch * kN + col0 + (c4 << 2));
    }
    __syncthreads();

    float acc[2][4][4];
#pragma unroll
    for (int s = 0; s < 2; s++)
#pragma unroll
        for (int ot = 0; ot < 4; ot++)
#pragma unroll
            for (int r = 0; r < 4; r++) acc[s][ot][r] = 0.f;

    uint32_t bfrag[2][4][2];
#pragma unroll
    for (int s = 0; s < 2; s++) {
        const int colb = ((warp + (s << 3)) << 3) + g;
#pragma unroll
        for (int ks = 0; ks < 4; ks++) {
            const int kc = (ks << 4) + t2;
            bfrag[s][ks][0] = pack_bf16x2(sXf[kc][colb],     sXf[kc + 1][colb]);
            bfrag[s][ks][1] = pack_bf16x2(sXf[kc + 8][colb], sXf[kc + 9][colb]);
        }
    }

#pragma unroll
    for (int ot = 0; ot < 4; ot++) {
#pragma unroll
        for (int ks = 0; ks < 4; ks++) {
            uint32_t a[4];
            const int ra = (ot << 4) + g, ca = (ks << 4) + t2;
            a[0] = ld_u32_bf(&sM[ra][ca]);     a[1] = ld_u32_bf(&sM[ra + 8][ca]);
            a[2] = ld_u32_bf(&sM[ra][ca + 8]); a[3] = ld_u32_bf(&sM[ra + 8][ca + 8]);
            mma_bf16(acc[0][ot], a, bfrag[0][ks]);
            mma_bf16(acc[1][ot], a, bfrag[1][ks]);
        }
    }

#pragma unroll
    for (int s = 0; s < 2; s++) {
        const int c0 = ((warp + (s << 3)) << 3) + t2;
#pragma unroll
        for (int ot = 0; ot < 4; ot++) {
            const int r0 = (ot << 4) + g;
            const float bp0 = __ldg(&bp[r0]), bp1 = __ldg(&bp[r0 + 8]);
            float2 v0, v1;
            v0.x = acc[s][ot][0] + sXf[r0][c0]         + bp0;
            v0.y = acc[s][ot][1] + sXf[r0][c0 + 1]     + bp0;
            v1.x = acc[s][ot][2] + sXf[r0 + 8][c0]     + bp1;
            v1.y = acc[s][ot][3] + sXf[r0 + 8][c0 + 1] + bp1;
            *reinterpret_cast<float2*>(&ob[(size_t)r0 * kN + col0 + c0]) = v0;
            *reinterpret_cast<float2*>(&ob[(size_t)(r0 + 8) * kN + col0 + c0]) = v1;
        }
    }
}

// ------------------------------------------------------------------ launch
extern "C" void kernel_launch(void* const* d_in, const int* in_sizes, int n_in,
                              void* d_out, int out_size) {
    const float* x       = (const float*)d_in[0];
    const float* Wq      = (const float*)d_in[1];
    const float* Wk      = (const float*)d_in[2];
    const float* Wv      = (const float*)d_in[3];
    const float* Wp      = (const float*)d_in[4];
    const float* bp      = (const float*)d_in[5];
    const float* rescale = (const float*)d_in[6];
    float* out           = (float*)d_out;

    syrk_kernel<<<kGrid1, 256>>>(x);
    attn_kernel<<<2, 256>>>(Wq, Wk, Wv, Wp, rescale);
    apply_kernel<<<2 * kNChunks, 256>>>(x, bp, out);
}

// round 6
// speedup vs baseline: 1.3873x; 1.3873x over previous
#include <cuda_runtime.h>
#include <cuda_bf16.h>
#include <stdint.h>
#include <stddef.h>

namespace {
constexpr int kC       = 64;
constexpr int kN       = 512 * 512;     // 262144
constexpr int kChunk   = 128;
constexpr int kNChunks = kN / kChunk;   // 2048
constexpr int kGrid1   = 592;           // syrk blocks (even: 2 batches interleaved), 2/SM
constexpr int kBPB     = kGrid1 / 2;    // 296 blocks per batch
constexpr int kP1      = 136;           // bf16 smem pitch (conflict-free)
constexpr int kPF      = 132;           // f32 smem pitch
constexpr int kPM      = 72;            // bf16 M pitch (conflict-free)
}

__device__ float g_part[kGrid1][kC][kC];
__device__ float g_xcov[2][kC][kC];
__device__ __nv_bfloat16 g_M[2][kC][kC];

__device__ __forceinline__ void mma_bf16(float c[4], const uint32_t a[4],
                                         const uint32_t b[2]) {
    asm volatile(
        "mma.sync.aligned.m16n8k16.row.col.f32.bf16.bf16.f32 "
        "{%0,%1,%2,%3}, {%4,%5,%6,%7}, {%8,%9}, {%0,%1,%2,%3};\n"
        : "+f"(c[0]), "+f"(c[1]), "+f"(c[2]), "+f"(c[3])
        : "r"(a[0]), "r"(a[1]), "r"(a[2]), "r"(a[3]), "r"(b[0]), "r"(b[1]));
}

__device__ __forceinline__ uint32_t ld_u32_bf(const __nv_bfloat16* p) {
    return *reinterpret_cast<const uint32_t*>(p);
}

__device__ __forceinline__ uint32_t pack_bf16x2(float lo, float hi) {
    __nv_bfloat162 h = __floats2bfloat162_rn(lo, hi);
    return *reinterpret_cast<uint32_t*>(&h);
}

// ------------------------------------------------------------------ pass 1
// Xcov partials: bf16 hi/lo split syrk. Per-warp: two 16x16 C tiles.
__global__ __launch_bounds__(256) void syrk_kernel(const float* __restrict__ x) {
    __shared__ __nv_bfloat16 sH[kC][kP1];
    __shared__ __nv_bfloat16 sL[kC][kP1];

    const int tid = threadIdx.x;
    const int warp = tid >> 5, lane = tid & 31;
    const int g = lane >> 2, t2 = (lane & 3) << 1;
    const int b = blockIdx.x & 1;
    const float* xb = x + (size_t)b * kC * kN;
    const int i0 = warp >> 2, j0 = warp & 3;   // C tile coords

    float acc[2][2][4];
#pragma unroll
    for (int s = 0; s < 2; s++)
#pragma unroll
        for (int n = 0; n < 2; n++)
#pragma unroll
            for (int r = 0; r < 4; r++) acc[s][n][r] = 0.f;

    float4 buf[8];
    int c = blockIdx.x >> 1;
    if (c < kNChunks) {
        const int col0 = c * kChunk;
#pragma unroll
        for (int i = 0; i < 8; i++) {
            const int idx4 = tid + (i << 8);
            buf[i] = *reinterpret_cast<const float4*>(
                xb + (size_t)(idx4 >> 5) * kN + col0 + ((idx4 & 31) << 2));
        }
    }

    for (; c < kNChunks; c += kBPB) {
#pragma unroll
        for (int i = 0; i < 8; i++) {
            const int idx4 = tid + (i << 8);
            const int ch = idx4 >> 5, cc = (idx4 & 31) << 2;
            float v[4] = {buf[i].x, buf[i].y, buf[i].z, buf[i].w};
            __nv_bfloat16 h[4], l[4];
#pragma unroll
            for (int k = 0; k < 4; k++) {
                h[k] = __float2bfloat16(v[k]);
                l[k] = __float2bfloat16(v[k] - __bfloat162float(h[k]));
            }
            *reinterpret_cast<__nv_bfloat162*>(&sH[ch][cc])     = __halves2bfloat162(h[0], h[1]);
            *reinterpret_cast<__nv_bfloat162*>(&sH[ch][cc + 2]) = __halves2bfloat162(h[2], h[3]);
            *reinterpret_cast<__nv_bfloat162*>(&sL[ch][cc])     = __halves2bfloat162(l[0], l[1]);
            *reinterpret_cast<__nv_bfloat162*>(&sL[ch][cc + 2]) = __halves2bfloat162(l[2], l[3]);
        }
        __syncthreads();

        const int nc = c + kBPB;                 // prefetch next chunk
        if (nc < kNChunks) {
            const int col0 = nc * kChunk;
#pragma unroll
            for (int i = 0; i < 8; i++) {
                const int idx4 = tid + (i << 8);
                buf[i] = *reinterpret_cast<const float4*>(
                    xb + (size_t)(idx4 >> 5) * kN + col0 + ((idx4 & 31) << 2));
            }
        }

#pragma unroll
        for (int ks = 0; ks < 8; ks++) {
            const int kc = (ks << 4) + t2;
#pragma unroll
            for (int s = 0; s < 2; s++) {
                const int ra = ((i0 + (s << 1)) << 4) + g;
                uint32_t aH[4], aL[4];
                aH[0] = ld_u32_bf(&sH[ra][kc]);     aH[1] = ld_u32_bf(&sH[ra + 8][kc]);
                aH[2] = ld_u32_bf(&sH[ra][kc + 8]); aH[3] = ld_u32_bf(&sH[ra + 8][kc + 8]);
                aL[0] = ld_u32_bf(&sL[ra][kc]);     aL[1] = ld_u32_bf(&sL[ra + 8][kc]);
                aL[2] = ld_u32_bf(&sL[ra][kc + 8]); aL[3] = ld_u32_bf(&sL[ra + 8][kc + 8]);
#pragma unroll
                for (int nh = 0; nh < 2; nh++) {
                    const int rb = (j0 << 4) + (nh << 3) + g;
                    uint32_t bH[2], bL[2];
                    bH[0] = ld_u32_bf(&sH[rb][kc]); bH[1] = ld_u32_bf(&sH[rb][kc + 8]);
                    bL[0] = ld_u32_bf(&sL[rb][kc]); bL[1] = ld_u32_bf(&sL[rb][kc + 8]);
                    mma_bf16(acc[s][nh], aH, bH);
                    mma_bf16(acc[s][nh], aH, bL);
                    mma_bf16(acc[s][nh], aL, bH);
                }
            }
        }
        __syncthreads();
    }

#pragma unroll
    for (int s = 0; s < 2; s++) {
        const int r0 = ((i0 + (s << 1)) << 4) + g;
#pragma unroll
        for (int nh = 0; nh < 2; nh++) {
            const int cb = (j0 << 4) + (nh << 3) + t2;
            g_part[blockIdx.x][r0][cb]         = acc[s][nh][0];
            g_part[blockIdx.x][r0][cb + 1]     = acc[s][nh][1];
            g_part[blockIdx.x][r0 + 8][cb]     = acc[s][nh][2];
            g_part[blockIdx.x][r0 + 8][cb + 1] = acc[s][nh][3];
        }
    }
}

// ------------------------------------------------------------------ pass 1b
// Parallel deterministic reduction of partials: grid = 2*64 blocks, one
// (batch,row) per block. 4 sub-accumulators per column, fixed combine tree.
__global__ __launch_bounds__(256) void reduce_kernel() {
    const int b   = blockIdx.x >> 6;
    const int r   = blockIdx.x & 63;
    const int col = threadIdx.x & 63;
    const int sub = threadIdx.x >> 6;          // 0..3
    __shared__ float sAcc[4][kC];

    constexpr int kPer = kBPB / 4;             // 74 partials per sub
    const int j0 = sub * kPer;
    float s0 = 0.f, s1 = 0.f;
#pragma unroll 2
    for (int i = 0; i < kPer; i += 2) {
        s0 += g_part[b + 2 * (j0 + i)][r][col];
        s1 += g_part[b + 2 * (j0 + i + 1)][r][col];
    }
    sAcc[sub][col] = s0 + s1;
    __syncthreads();
    if (sub == 0)
        g_xcov[b][r][col] = (sAcc[0][col] + sAcc[1][col]) +
                            (sAcc[2][col] + sAcc[3][col]);
}

// ------------------------------------------------------------------ pass 2
// Norms, per-head softmax, M = Wp * A * Wv. All 64x64, negligible cost.
__global__ __launch_bounds__(256) void attn_kernel(
    const float* __restrict__ Wq, const float* __restrict__ Wk,
    const float* __restrict__ Wv, const float* __restrict__ Wp,
    const float* __restrict__ rescale)
{
    __shared__ float sXc[kC][kC + 1];
    __shared__ float sT[kC][kC + 1];
    __shared__ float sAttn[kC][16];
    __shared__ float sSq[kC], sSk[kC];

    const int b = blockIdx.x, tid = threadIdx.x;

    for (int idx = tid; idx < kC * kC; idx += 256)
        sXc[idx >> 6][idx & 63] = g_xcov[b][idx >> 6][idx & 63];
    __syncthreads();

    for (int idx = tid; idx < kC * kC; idx += 256) {   // Tq = Wq * Xc
        const int r = idx >> 6, m = idx & 63;
        float s = 0.f;
#pragma unroll 8
        for (int j = 0; j < 64; j++) s += __ldg(&Wq[(r << 6) + j]) * sXc[j][m];
        sT[r][m] = s;
    }
    __syncthreads();

    if (tid < 64) {                                    // ||q_c||
        float s = 0.f;
        for (int m = 0; m < 64; m++) s += sT[tid][m] * __ldg(&Wq[(tid << 6) + m]);
        sSq[tid] = fmaxf(sqrtf(fmaxf(s, 0.f)), 1e-12f);
    }
    __syncthreads();

    for (int idx = tid; idx < 1024; idx += 256) {      // per-head G = Wk Xc Wq^T
        const int h = idx >> 8, d = (idx >> 4) & 15, e = idx & 15;
        const int kc = (h << 4) + d, qc = (h << 4) + e;
        float s = 0.f;
#pragma unroll 8
        for (int m = 0; m < 64; m++) s += __ldg(&Wk[(kc << 6) + m]) * sT[qc][m];
        sAttn[kc][e] = s;
    }
    __syncthreads();

    for (int idx = tid; idx < kC * kC; idx += 256) {   // Tk = Wk * Xc
        const int r = idx >> 6, m = idx & 63;
        float s = 0.f;
#pragma unroll 8
        for (int j = 0; j < 64; j++) s += __ldg(&Wk[(r << 6) + j]) * sXc[j][m];
        sT[r][m] = s;
    }
    __syncthreads();

    if (tid < 64) {                                    // ||k_c||
        float s = 0.f;
        for (int m = 0; m < 64; m++) s += sT[tid][m] * __ldg(&Wk[(tid << 6) + m]);
        sSk[tid] = fmaxf(sqrtf(fmaxf(s, 0.f)), 1e-12f);
    }
    __syncthreads();

    if (tid < 64) {                                    // rescale + softmax(e)
        const int kc = tid, h = kc >> 4;
        const float rs = __ldg(&rescale[h]);
        const float invk = 1.f / sSk[kc];
        float logit[16], mx = -1e30f;
#pragma unroll
        for (int e = 0; e < 16; e++) {
            logit[e] = sAttn[kc][e] * invk / sSq[(kc & 48) + e] * rs;
            mx = fmaxf(mx, logit[e]);
        }
        float sum = 0.f;
#pragma unroll
        for (int e = 0; e < 16; e++) { logit[e] = expf(logit[e] - mx); sum += logit[e]; }
        const float inv = 1.f / sum;
#pragma unroll
        for (int e = 0; e < 16; e++) sAttn[kc][e] = logit[e] * inv;
    }
    __syncthreads();

    for (int idx = tid; idx < kC * kC; idx += 256) {   // R = A_blockdiag * Wv
        const int r = idx >> 6, cc = idx & 63, h = r >> 4;
        float s = 0.f;
#pragma unroll
        for (int e = 0; e < 16; e++)
            s += sAttn[r][e] * __ldg(&Wv[(((h << 4) + e) << 6) + cc]);
        sXc[r][cc] = s;
    }
    __syncthreads();

    for (int idx = tid; idx < kC * kC; idx += 256) {   // M = Wp * R -> bf16
        const int o = idx >> 6, cc = idx & 63;
        float s = 0.f;
#pragma unroll 8
        for (int j = 0; j < 64; j++) s += __ldg(&Wp[(o << 6) + j]) * sXc[j][cc];
        g_M[b][o][cc] = __float2bfloat16(s);
    }
}

// ------------------------------------------------------------------ pass 3
// out = x + M x + bp.  One 64x128 chunk per block; residual fp32, Mx via mma.
__global__ __launch_bounds__(256) void apply_kernel(
    const float* __restrict__ x, const float* __restrict__ bp,
    float* __restrict__ out)
{
    __shared__ float sXf[kC][kPF];
    __shared__ __nv_bfloat16 sM[kC][kPM];

    const int tid = threadIdx.x;
    const int warp = tid >> 5, lane = tid & 31;
    const int g = lane >> 2, t2 = (lane & 3) << 1;
    const int gid = blockIdx.x;
    const int b = gid >> 11;
    const int col0 = (gid & 2047) * kChunk;
    const float* xb = x + (size_t)b * kC * kN;
    float* ob = out + (size_t)b * kC * kN;

    for (int idx = tid; idx < kC * kC; idx += 256)
        sM[idx >> 6][idx & 63] = g_M[b][idx >> 6][idx & 63];

#pragma unroll
    for (int i = 0; i < 8; i++) {
        const int idx4 = tid + (i << 8);
        const int ch = idx4 >> 5, c4 = idx4 & 31;
        *reinterpret_cast<float4*>(&sXf[ch][c4 << 2]) =
            *reinterpret_cast<const float4*>(xb + (size_t)ch * kN + col0 + (c4 << 2));
    }
    __syncthreads();

    float acc[2][4][4];
#pragma unroll
    for (int s = 0; s < 2; s++)
#pragma unroll
        for (int ot = 0; ot < 4; ot++)
#pragma unroll
            for (int r = 0; r < 4; r++) acc[s][ot][r] = 0.f;

    uint32_t bfrag[2][4][2];
#pragma unroll
    for (int s = 0; s < 2; s++) {
        const int colb = ((warp + (s << 3)) << 3) + g;
#pragma unroll
        for (int ks = 0; ks < 4; ks++) {
            const int kc = (ks << 4) + t2;
            bfrag[s][ks][0] = pack_bf16x2(sXf[kc][colb],     sXf[kc + 1][colb]);
            bfrag[s][ks][1] = pack_bf16x2(sXf[kc + 8][colb], sXf[kc + 9][colb]);
        }
    }

#pragma unroll
    for (int ot = 0; ot < 4; ot++) {
#pragma unroll
        for (int ks = 0; ks < 4; ks++) {
            uint32_t a[4];
            const int ra = (ot << 4) + g, ca = (ks << 4) + t2;
            a[0] = ld_u32_bf(&sM[ra][ca]);     a[1] = ld_u32_bf(&sM[ra + 8][ca]);
            a[2] = ld_u32_bf(&sM[ra][ca + 8]); a[3] = ld_u32_bf(&sM[ra + 8][ca + 8]);
            mma_bf16(acc[0][ot], a, bfrag[0][ks]);
            mma_bf16(acc[1][ot], a, bfrag[1][ks]);
        }
    }

#pragma unroll
    for (int s = 0; s < 2; s++) {
        const int c0 = ((warp + (s << 3)) << 3) + t2;
#pragma unroll
        for (int ot = 0; ot < 4; ot++) {
            const int r0 = (ot << 4) + g;
            const float bp0 = __ldg(&bp[r0]), bp1 = __ldg(&bp[r0 + 8]);
            float2 v0, v1;
            v0.x = acc[s][ot][0] + sXf[r0][c0]         + bp0;
            v0.y = acc[s][ot][1] + sXf[r0][c0 + 1]     + bp0;
            v1.x = acc[s][ot][2] + sXf[r0 + 8][c0]     + bp1;
            v1.y = acc[s][ot][3] + sXf[r0 + 8][c0 + 1] + bp1;
            *reinterpret_cast<float2*>(&ob[(size_t)r0 * kN + col0 + c0]) = v0;
            *reinterpret_cast<float2*>(&ob[(size_t)(r0 + 8) * kN + col0 + c0]) = v1;
        }
    }
}

// ------------------------------------------------------------------ launch
extern "C" void kernel_launch(void* const* d_in, const int* in_sizes, int n_in,
                              void* d_out, int out_size) {
    const float* x       = (const float*)d_in[0];
    const float* Wq      = (const float*)d_in[1];
    const float* Wk      = (const float*)d_in[2];
    const float* Wv      = (const float*)d_in[3];
    const float* Wp      = (const float*)d_in[4];
    const float* bp      = (const float*)d_in[5];
    const float* rescale = (const float*)d_in[6];
    float* out           = (float*)d_out;

    syrk_kernel<<<kGrid1, 256>>>(x);
    reduce_kernel<<<2 * kC, 256>>>();
    attn_kernel<<<2, 256>>>(Wq, Wk, Wv, Wp, rescale);
    apply_kernel<<<2 * kNChunks, 256>>>(x, bp, out);
}

// round 8
// speedup vs baseline: 1.8116x; 1.3058x over previous
#include <cuda_runtime.h>
#include <cuda_bf16.h>
#include <stdint.h>
#include <stddef.h>

namespace {
constexpr int kC       = 64;
constexpr int kN       = 512 * 512;     // 262144
constexpr int kChunk   = 128;
constexpr int kNChunks = kN / kChunk;   // 2048
constexpr int kGrid1   = 592;           // syrk blocks (even: 2 batches interleaved)
constexpr int kBPB     = kGrid1 / 2;    // 296 blocks per batch
constexpr int kP1      = 136;           // bf16 smem pitch (conflict-free)
constexpr int kPF      = 132;           // f32 smem pitch
constexpr int kPM      = 72;            // bf16 M pitch (conflict-free)
}

__device__ float g_part[kGrid1][kC][kC];     // per-block U = 0.5*HH^T + HL^T
__device__ float g_xcov[2][kC][kC];          // summed U
__device__ float g_xcov_sym[2][kC][kC];      // Xc = U + U^T
__device__ __nv_bfloat16 g_M[2][kC][kC];

__device__ __forceinline__ void mma_bf16(float c[4], const uint32_t a[4],
                                         const uint32_t b[2]) {
    asm volatile(
        "mma.sync.aligned.m16n8k16.row.col.f32.bf16.bf16.f32 "
        "{%0,%1,%2,%3}, {%4,%5,%6,%7}, {%8,%9}, {%0,%1,%2,%3};\n"
        : "+f"(c[0]), "+f"(c[1]), "+f"(c[2]), "+f"(c[3])
        : "r"(a[0]), "r"(a[1]), "r"(a[2]), "r"(a[3]), "r"(b[0]), "r"(b[1]));
}

__device__ __forceinline__ uint32_t ld_u32_bf(const __nv_bfloat16* p) {
    return *reinterpret_cast<const uint32_t*>(p);
}

__device__ __forceinline__ uint32_t pack_bf16x2(float lo, float hi) {
    __nv_bfloat162 h = __floats2bfloat162_rn(lo, hi);
    return *reinterpret_cast<uint32_t*>(&h);
}

// ------------------------------------------------------------------ pass 1
// U partials: U = 0.5*H H^T + H L^T  (Xcov = sum(U + U^T); LL^T dropped)
__global__ __launch_bounds__(256, 2) void syrk_kernel(const float* __restrict__ x) {
    __shared__ __nv_bfloat16 sH[kC][kP1];
    __shared__ __nv_bfloat16 sL[kC][kP1];

    const int tid = threadIdx.x;
    const int warp = tid >> 5, lane = tid & 31;
    const int g = lane >> 2, t2 = (lane & 3) << 1;
    const int b = blockIdx.x & 1;
    const float* xb = x + (size_t)b * kC * kN;
    const int i0 = warp >> 2, j0 = warp & 3;   // C tile coords

    float accS[2][2][4];   // H H^T
    float accX[2][2][4];   // H L^T
#pragma unroll
    for (int s = 0; s < 2; s++)
#pragma unroll
        for (int n = 0; n < 2; n++)
#pragma unroll
            for (int r = 0; r < 4; r++) { accS[s][n][r] = 0.f; accX[s][n][r] = 0.f; }

    float4 buf[8];
    int c = blockIdx.x >> 1;
    if (c < kNChunks) {
        const int col0 = c * kChunk;
#pragma unroll
        for (int i = 0; i < 8; i++) {
            const int idx4 = tid + (i << 8);
            buf[i] = *reinterpret_cast<const float4*>(
                xb + (size_t)(idx4 >> 5) * kN + col0 + ((idx4 & 31) << 2));
        }
    }

    for (; c < kNChunks; c += kBPB) {
#pragma unroll
        for (int i = 0; i < 8; i++) {
            const int idx4 = tid + (i << 8);
            const int ch = idx4 >> 5, cc = (idx4 & 31) << 2;
            float v[4] = {buf[i].x, buf[i].y, buf[i].z, buf[i].w};
            __nv_bfloat16 h[4], l[4];
#pragma unroll
            for (int k = 0; k < 4; k++) {
                h[k] = __float2bfloat16(v[k]);
                l[k] = __float2bfloat16(v[k] - __bfloat162float(h[k]));
            }
            *reinterpret_cast<__nv_bfloat162*>(&sH[ch][cc])     = __halves2bfloat162(h[0], h[1]);
            *reinterpret_cast<__nv_bfloat162*>(&sH[ch][cc + 2]) = __halves2bfloat162(h[2], h[3]);
            *reinterpret_cast<__nv_bfloat162*>(&sL[ch][cc])     = __halves2bfloat162(l[0], l[1]);
            *reinterpret_cast<__nv_bfloat162*>(&sL[ch][cc + 2]) = __halves2bfloat162(l[2], l[3]);
        }
        __syncthreads();

        const int nc = c + kBPB;                 // prefetch next chunk
        if (nc < kNChunks) {
            const int col0 = nc * kChunk;
#pragma unroll
            for (int i = 0; i < 8; i++) {
                const int idx4 = tid + (i << 8);
                buf[i] = *reinterpret_cast<const float4*>(
                    xb + (size_t)(idx4 >> 5) * kN + col0 + ((idx4 & 31) << 2));
            }
        }

#pragma unroll
        for (int ks = 0; ks < 8; ks++) {
            const int kc = (ks << 4) + t2;
#pragma unroll
            for (int s = 0; s < 2; s++) {
                const int ra = ((i0 + (s << 1)) << 4) + g;
                uint32_t aH[4];
                aH[0] = ld_u32_bf(&sH[ra][kc]);     aH[1] = ld_u32_bf(&sH[ra + 8][kc]);
                aH[2] = ld_u32_bf(&sH[ra][kc + 8]); aH[3] = ld_u32_bf(&sH[ra + 8][kc + 8]);
#pragma unroll
                for (int nh = 0; nh < 2; nh++) {
                    const int rb = (j0 << 4) + (nh << 3) + g;
                    uint32_t bH[2], bL[2];
                    bH[0] = ld_u32_bf(&sH[rb][kc]); bH[1] = ld_u32_bf(&sH[rb][kc + 8]);
                    bL[0] = ld_u32_bf(&sL[rb][kc]); bL[1] = ld_u32_bf(&sL[rb][kc + 8]);
                    mma_bf16(accS[s][nh], aH, bH);
                    mma_bf16(accX[s][nh], aH, bL);
                }
            }
        }
        __syncthreads();
    }

#pragma unroll
    for (int s = 0; s < 2; s++) {
        const int r0 = ((i0 + (s << 1)) << 4) + g;
#pragma unroll
        for (int nh = 0; nh < 2; nh++) {
            const int cb = (j0 << 4) + (nh << 3) + t2;
            g_part[blockIdx.x][r0][cb]         = 0.5f * accS[s][nh][0] + accX[s][nh][0];
            g_part[blockIdx.x][r0][cb + 1]     = 0.5f * accS[s][nh][1] + accX[s][nh][1];
            g_part[blockIdx.x][r0 + 8][cb]     = 0.5f * accS[s][nh][2] + accX[s][nh][2];
            g_part[blockIdx.x][r0 + 8][cb + 1] = 0.5f * accS[s][nh][3] + accX[s][nh][3];
        }
    }
}

// ------------------------------------------------------------------ pass 1b
// Parallel deterministic reduction: one (batch,row) per block.
__global__ __launch_bounds__(256) void reduce_kernel() {
    const int b   = blockIdx.x >> 6;
    const int r   = blockIdx.x & 63;
    const int col = threadIdx.x & 63;
    const int sub = threadIdx.x >> 6;          // 0..3
    __shared__ float sAcc[4][kC];

    constexpr int kPer = kBPB / 4;             // 74 partials per sub
    const int j0 = sub * kPer;
    float s0 = 0.f, s1 = 0.f;
#pragma unroll 2
    for (int i = 0; i < kPer; i += 2) {
        s0 += g_part[b + 2 * (j0 + i)][r][col];
        s1 += g_part[b + 2 * (j0 + i + 1)][r][col];
    }
    sAcc[sub][col] = s0 + s1;
    __syncthreads();
    if (sub == 0)
        g_xcov[b][r][col] = (sAcc[0][col] + sAcc[1][col]) +
                            (sAcc[2][col] + sAcc[3][col]);
}

// ------------------------------------------------------------------ pass 1c
// Symmetrize: Xc = U + U^T (2 blocks, trivially cheap).
__global__ __launch_bounds__(256) void sym_kernel() {
    const int b = blockIdx.x;
    for (int idx = threadIdx.x; idx < kC * kC; idx += 256) {
        const int r = idx >> 6, c = idx & 63;
        g_xcov_sym[b][r][c] = g_xcov[b][r][c] + g_xcov[b][c][r];
    }
}

// ------------------------------------------------------------------ pass 2
// Norms, per-head softmax, M = Wp * A * Wv. Xc read from global (L1-hot).
__global__ __launch_bounds__(256) void attn_kernel(
    const float* __restrict__ Wq, const float* __restrict__ Wk,
    const float* __restrict__ Wv, const float* __restrict__ Wp,
    const float* __restrict__ rescale)
{
    __shared__ float sT[kC][kC + 1];
    __shared__ float sW[kC][kC + 1];
    __shared__ float sAttn[kC][16];
    __shared__ float sPart[4][kC];
    __shared__ float sSq[kC], sSk[kC];

    const int b = blockIdx.x, tid = threadIdx.x;
    const int m = tid & 63, quad = tid >> 6;   // quad uniform per warp

    const float* Xc = &g_xcov_sym[b][0][0];

    // load Wq
    for (int idx = tid; idx < kC * kC; idx += 256) sW[idx >> 6][idx & 63] = Wq[idx];
    __syncthreads();

    // Tq = Wq * Xc  (thread: column m, rows quad+4t)
    {
        float acc[16];
#pragma unroll
        for (int t = 0; t < 16; t++) acc[t] = 0.f;
#pragma unroll 4
        for (int j = 0; j < 64; j++) {
            const float xv = __ldg(&Xc[(j << 6) + m]);   // coalesced, L1-hot
#pragma unroll
            for (int t = 0; t < 16; t++) acc[t] += sW[quad + 4 * t][j] * xv;
        }
#pragma unroll
        for (int t = 0; t < 16; t++) sT[quad + 4 * t][m] = acc[t];
    }
    __syncthreads();

    // ||q_c||: partial dot(Tq[c], Wq[c]) per quad
    {
        float s = 0.f;
#pragma unroll
        for (int jj = 0; jj < 16; jj++) {
            const int j = quad * 16 + jj;
            s += sT[m][j] * sW[m][j];
        }
        sPart[quad][m] = s;
    }
    __syncthreads();
    if (tid < 64) {
        const float s = (sPart[0][tid] + sPart[1][tid]) +
                        (sPart[2][tid] + sPart[3][tid]);
        sSq[tid] = fmaxf(sqrtf(fmaxf(s, 0.f)), 1e-12f);
    }
    __syncthreads();

    // load Wk
    for (int idx = tid; idx < kC * kC; idx += 256) sW[idx >> 6][idx & 63] = Wk[idx];
    __syncthreads();

    // per-head logits G[kc][e] = dot(Wk[kc], Tq[qc])
    for (int idx = tid; idx < 1024; idx += 256) {
        const int h = idx >> 8, d = (idx >> 4) & 15, e = idx & 15;
        const int kc = (h << 4) + d, qc = (h << 4) + e;
        float s = 0.f;
#pragma unroll 8
        for (int mm = 0; mm < 64; mm++) s += sW[kc][mm] * sT[qc][mm];
        sAttn[kc][e] = s;
    }
    __syncthreads();

    // Tk = Wk * Xc (overwrite sT)
    {
        float acc[16];
#pragma unroll
        for (int t = 0; t < 16; t++) acc[t] = 0.f;
#pragma unroll 4
        for (int j = 0; j < 64; j++) {
            const float xv = __ldg(&Xc[(j << 6) + m]);
#pragma unroll
            for (int t = 0; t < 16; t++) acc[t] += sW[quad + 4 * t][j] * xv;
        }
#pragma unroll
        for (int t = 0; t < 16; t++) sT[quad + 4 * t][m] = acc[t];
    }
    __syncthreads();

    // ||k_c||
    {
        float s = 0.f;
#pragma unroll
        for (int jj = 0; jj < 16; jj++) {
            const int j = quad * 16 + jj;
            s += sT[m][j] * sW[m][j];
        }
        sPart[quad][m] = s;
    }
    __syncthreads();
    if (tid < 64) {
        const float s = (sPart[0][tid] + sPart[1][tid]) +
                        (sPart[2][tid] + sPart[3][tid]);
        sSk[tid] = fmaxf(sqrtf(fmaxf(s, 0.f)), 1e-12f);
    }
    __syncthreads();

    // rescale + softmax over e
    if (tid < 64) {
        const int kc = tid, h = kc >> 4;
        const float rs = __ldg(&rescale[h]);
        const float invk = 1.f / sSk[kc];
        float logit[16], mx = -1e30f;
#pragma unroll
        for (int e = 0; e < 16; e++) {
            logit[e] = sAttn[kc][e] * invk / sSq[(kc & 48) + e] * rs;
            mx = fmaxf(mx, logit[e]);
        }
        float sum = 0.f;
#pragma unroll
        for (int e = 0; e < 16; e++) { logit[e] = expf(logit[e] - mx); sum += logit[e]; }
        const float inv = 1.f / sum;
#pragma unroll
        for (int e = 0; e < 16; e++) sAttn[kc][e] = logit[e] * inv;
    }
    __syncthreads();

    // load Wv
    for (int idx = tid; idx < kC * kC; idx += 256) sW[idx >> 6][idx & 63] = Wv[idx];
    __syncthreads();

    // R = A_blockdiag * Wv -> sT (Tk dead)
    for (int idx = tid; idx < kC * kC; idx += 256) {
        const int r = idx >> 6, cc = idx & 63, h = r >> 4;
        float s = 0.f;
#pragma unroll
        for (int e = 0; e < 16; e++) s += sAttn[r][e] * sW[(h << 4) + e][cc];
        sT[r][cc] = s;
    }
    __syncthreads();

    // load Wp
    for (int idx = tid; idx < kC * kC; idx += 256) sW[idx >> 6][idx & 63] = Wp[idx];
    __syncthreads();

    // M = Wp * R -> bf16
    {
        float acc[16];
#pragma unroll
        for (int t = 0; t < 16; t++) acc[t] = 0.f;
#pragma unroll 4
        for (int j = 0; j < 64; j++) {
            const float xv = sT[j][m];
#pragma unroll
            for (int t = 0; t < 16; t++) acc[t] += sW[quad + 4 * t][j] * xv;
        }
#pragma unroll
        for (int t = 0; t < 16; t++)
            g_M[b][quad + 4 * t][m] = __float2bfloat16(acc[t]);
    }
}

// ------------------------------------------------------------------ pass 3
// out = x + M x + bp. Two 64x128 chunks per block, register double-buffered.
__global__ __launch_bounds__(256) void apply_kernel(
    const float* __restrict__ x, const float* __restrict__ bp,
    float* __restrict__ out)
{
    __shared__ float sXf[kC][kPF];
    __shared__ __nv_bfloat16 sM[kC][kPM];

    const int tid = threadIdx.x;
    const int warp = tid >> 5, lane = tid & 31;
    const int g = lane >> 2, t2 = (lane & 3) << 1;
    const int gid = blockIdx.x;
    const int b = gid >> 10;                 // 1024 block-slots per batch
    const int c0idx = gid & 1023;            // handles chunks c0idx, c0idx+1024
    const float* xb = x + (size_t)b * kC * kN;
    float* ob = out + (size_t)b * kC * kN;

    for (int idx = tid; idx < kC * kC; idx += 256)
        sM[idx >> 6][idx & 63] = g_M[b][idx >> 6][idx & 63];

    float4 buf[8];
    {
        const int col0 = c0idx * kChunk;
#pragma unroll
        for (int i = 0; i < 8; i++) {
            const int idx4 = tid + (i << 8);
            buf[i] = *reinterpret_cast<const float4*>(
                xb + (size_t)(idx4 >> 5) * kN + col0 + ((idx4 & 31) << 2));
        }
    }

#pragma unroll
    for (int it = 0; it < 2; it++) {
        const int col0 = (c0idx + (it << 10)) * kChunk;
        if (it) __syncthreads();             // epilogue reads of prev tile done
#pragma unroll
        for (int i = 0; i < 8; i++) {
            const int idx4 = tid + (i << 8);
            *reinterpret_cast<float4*>(&sXf[idx4 >> 5][(idx4 & 31) << 2]) = buf[i];
        }
        __syncthreads();

        if (it == 0) {                        // prefetch second chunk
            const int ncol0 = (c0idx + 1024) * kChunk;
#pragma unroll
            for (int i = 0; i < 8; i++) {
                const int idx4 = tid + (i << 8);
                buf[i] = *reinterpret_cast<const float4*>(
                    xb + (size_t)(idx4 >> 5) * kN + ncol0 + ((idx4 & 31) << 2));
            }
        }

        float acc[2][4][4];
#pragma unroll
        for (int s = 0; s < 2; s++)
#pragma unroll
            for (int ot = 0; ot < 4; ot++)
#pragma unroll
                for (int r = 0; r < 4; r++) acc[s][ot][r] = 0.f;

        uint32_t bfrag[2][4][2];
#pragma unroll
        for (int s = 0; s < 2; s++) {
            const int colb = ((warp + (s << 3)) << 3) + g;
#pragma unroll
            for (int ks = 0; ks < 4; ks++) {
                const int kc = (ks << 4) + t2;
                bfrag[s][ks][0] = pack_bf16x2(sXf[kc][colb],     sXf[kc + 1][colb]);
                bfrag[s][ks][1] = pack_bf16x2(sXf[kc + 8][colb], sXf[kc + 9][colb]);
            }
        }

#pragma unroll
        for (int ot = 0; ot < 4; ot++) {
#pragma unroll
            for (int ks = 0; ks < 4; ks++) {
                uint32_t a[4];
                const int ra = (ot << 4) + g, ca = (ks << 4) + t2;
                a[0] = ld_u32_bf(&sM[ra][ca]);     a[1] = ld_u32_bf(&sM[ra + 8][ca]);
                a[2] = ld_u32_bf(&sM[ra][ca + 8]); a[3] = ld_u32_bf(&sM[ra + 8][ca + 8]);
                mma_bf16(acc[0][ot], a, bfrag[0][ks]);
                mma_bf16(acc[1][ot], a, bfrag[1][ks]);
            }
        }

#pragma unroll
        for (int s = 0; s < 2; s++) {
            const int c0 = ((warp + (s << 3)) << 3) + t2;
#pragma unroll
            for (int ot = 0; ot < 4; ot++) {
                const int r0 = (ot << 4) + g;
                const float bp0 = __ldg(&bp[r0]), bp1 = __ldg(&bp[r0 + 8]);
                float2 v0, v1;
                v0.x = acc[s][ot][0] + sXf[r0][c0]         + bp0;
                v0.y = acc[s][ot][1] + sXf[r0][c0 + 1]     + bp0;
                v1.x = acc[s][ot][2] + sXf[r0 + 8][c0]     + bp1;
                v1.y = acc[s][ot][3] + sXf[r0 + 8][c0 + 1] + bp1;
                *reinterpret_cast<float2*>(&ob[(size_t)r0 * kN + col0 + c0]) = v0;
                *reinterpret_cast<float2*>(&ob[(size_t)(r0 + 8) * kN + col0 + c0]) = v1;
            }
        }
    }
}

// ------------------------------------------------------------------ launch
extern "C" void kernel_launch(void* const* d_in, const int* in_sizes, int n_in,
                              void* d_out, int out_size) {
    const float* x       = (const float*)d_in[0];
    const float* Wq      = (const float*)d_in[1];
    const float* Wk      = (const float*)d_in[2];
    const float* Wv      = (const float*)d_in[3];
    const float* Wp      = (const float*)d_in[4];
    const float* bp      = (const float*)d_in[5];
    const float* rescale = (const float*)d_in[6];
    float* out           = (float*)d_out;

    syrk_kernel<<<kGrid1, 256>>>(x);
    reduce_kernel<<<2 * kC, 256>>>();
    sym_kernel<<<2, 256>>>();
    attn_kernel<<<2, 256>>>(Wq, Wk, Wv, Wp, rescale);
    apply_kernel<<<2048, 256>>>(x, bp, out);
}

// round 9
// speedup vs baseline: 2.1978x; 1.2132x over previous
#include <cuda_runtime.h>
#include <cuda_bf16.h>
#include <stdint.h>
#include <stddef.h>

namespace {
constexpr int kC       = 64;
constexpr int kN       = 512 * 512;     // 262144
constexpr int kChunk   = 128;
constexpr int kNChunks = kN / kChunk;   // 2048
constexpr int kGrid1   = 592;           // syrk blocks (even: 2 batches interleaved)
constexpr int kBPB     = kGrid1 / 2;    // 296 blocks per batch
constexpr int kP1      = 136;           // bf16 smem pitch (conflict-free)
constexpr int kPF      = 132;           // f32 smem pitch
constexpr int kPM      = 72;            // bf16 M pitch (conflict-free)
constexpr int kPA      = 65;            // attn f32 pitch
constexpr int kAttnSmem = 4 * kC * kPA * 4;   // 4 buffers: Xc, W0, W1, T
}

__device__ float g_part[kGrid1][kC][kC];     // per-block U = 0.5*HH^T + HL^T
__device__ float g_xcov[2][kC][kC];          // summed U (Xc = U + U^T at use)
__device__ __nv_bfloat16 g_M[2][kC][kC];

__device__ __forceinline__ void mma_bf16(float c[4], const uint32_t a[4],
                                         const uint32_t b[2]) {
    asm volatile(
        "mma.sync.aligned.m16n8k16.row.col.f32.bf16.bf16.f32 "
        "{%0,%1,%2,%3}, {%4,%5,%6,%7}, {%8,%9}, {%0,%1,%2,%3};\n"
        : "+f"(c[0]), "+f"(c[1]), "+f"(c[2]), "+f"(c[3])
        : "r"(a[0]), "r"(a[1]), "r"(a[2]), "r"(a[3]), "r"(b[0]), "r"(b[1]));
}

__device__ __forceinline__ uint32_t ld_u32_bf(const __nv_bfloat16* p) {
    return *reinterpret_cast<const uint32_t*>(p);
}

__device__ __forceinline__ uint32_t pack_bf16x2(float lo, float hi) {
    __nv_bfloat162 h = __floats2bfloat162_rn(lo, hi);
    return *reinterpret_cast<uint32_t*>(&h);
}

// ------------------------------------------------------------------ pass 1
// U partials: U = 0.5*H H^T + H L^T  (Xcov = sum(U + U^T); LL^T dropped)
__global__ __launch_bounds__(256, 2) void syrk_kernel(const float* __restrict__ x) {
    __shared__ __nv_bfloat16 sH[kC][kP1];
    __shared__ __nv_bfloat16 sL[kC][kP1];

    const int tid = threadIdx.x;
    const int warp = tid >> 5, lane = tid & 31;
    const int g = lane >> 2, t2 = (lane & 3) << 1;
    const int b = blockIdx.x & 1;
    const float* xb = x + (size_t)b * kC * kN;
    const int i0 = warp >> 2, j0 = warp & 3;   // C tile coords

    float accS[2][2][4];   // H H^T
    float accX[2][2][4];   // H L^T
#pragma unroll
    for (int s = 0; s < 2; s++)
#pragma unroll
        for (int n = 0; n < 2; n++)
#pragma unroll
            for (int r = 0; r < 4; r++) { accS[s][n][r] = 0.f; accX[s][n][r] = 0.f; }

    float4 buf[8];
    int c = blockIdx.x >> 1;
    if (c < kNChunks) {
        const int col0 = c * kChunk;
#pragma unroll
        for (int i = 0; i < 8; i++) {
            const int idx4 = tid + (i << 8);
            buf[i] = *reinterpret_cast<const float4*>(
                xb + (size_t)(idx4 >> 5) * kN + col0 + ((idx4 & 31) << 2));
        }
    }

    for (; c < kNChunks; c += kBPB) {
#pragma unroll
        for (int i = 0; i < 8; i++) {
            const int idx4 = tid + (i << 8);
            const int ch = idx4 >> 5, cc = (idx4 & 31) << 2;
            float v[4] = {buf[i].x, buf[i].y, buf[i].z, buf[i].w};
            __nv_bfloat16 h[4], l[4];
#pragma unroll
            for (int k = 0; k < 4; k++) {
                h[k] = __float2bfloat16(v[k]);
                l[k] = __float2bfloat16(v[k] - __bfloat162float(h[k]));
            }
            *reinterpret_cast<__nv_bfloat162*>(&sH[ch][cc])     = __halves2bfloat162(h[0], h[1]);
            *reinterpret_cast<__nv_bfloat162*>(&sH[ch][cc + 2]) = __halves2bfloat162(h[2], h[3]);
            *reinterpret_cast<__nv_bfloat162*>(&sL[ch][cc])     = __halves2bfloat162(l[0], l[1]);
            *reinterpret_cast<__nv_bfloat162*>(&sL[ch][cc + 2]) = __halves2bfloat162(l[2], l[3]);
        }
        __syncthreads();

        const int nc = c + kBPB;                 // prefetch next chunk
        if (nc < kNChunks) {
            const int col0 = nc * kChunk;
#pragma unroll
            for (int i = 0; i < 8; i++) {
                const int idx4 = tid + (i << 8);
                buf[i] = *reinterpret_cast<const float4*>(
                    xb + (size_t)(idx4 >> 5) * kN + col0 + ((idx4 & 31) << 2));
            }
        }

#pragma unroll
        for (int ks = 0; ks < 8; ks++) {
            const int kc = (ks << 4) + t2;
#pragma unroll
            for (int s = 0; s < 2; s++) {
                const int ra = ((i0 + (s << 1)) << 4) + g;
                uint32_t aH[4];
                aH[0] = ld_u32_bf(&sH[ra][kc]);     aH[1] = ld_u32_bf(&sH[ra + 8][kc]);
                aH[2] = ld_u32_bf(&sH[ra][kc + 8]); aH[3] = ld_u32_bf(&sH[ra + 8][kc + 8]);
#pragma unroll
                for (int nh = 0; nh < 2; nh++) {
                    const int rb = (j0 << 4) + (nh << 3) + g;
                    uint32_t bH[2], bL[2];
                    bH[0] = ld_u32_bf(&sH[rb][kc]); bH[1] = ld_u32_bf(&sH[rb][kc + 8]);
                    bL[0] = ld_u32_bf(&sL[rb][kc]); bL[1] = ld_u32_bf(&sL[rb][kc + 8]);
                    mma_bf16(accS[s][nh], aH, bH);
                    mma_bf16(accX[s][nh], aH, bL);
                }
            }
        }
        __syncthreads();
    }

#pragma unroll
    for (int s = 0; s < 2; s++) {
        const int r0 = ((i0 + (s << 1)) << 4) + g;
#pragma unroll
        for (int nh = 0; nh < 2; nh++) {
            const int cb = (j0 << 4) + (nh << 3) + t2;
            g_part[blockIdx.x][r0][cb]         = 0.5f * accS[s][nh][0] + accX[s][nh][0];
            g_part[blockIdx.x][r0][cb + 1]     = 0.5f * accS[s][nh][1] + accX[s][nh][1];
            g_part[blockIdx.x][r0 + 8][cb]     = 0.5f * accS[s][nh][2] + accX[s][nh][2];
            g_part[blockIdx.x][r0 + 8][cb + 1] = 0.5f * accS[s][nh][3] + accX[s][nh][3];
        }
    }
}

// ------------------------------------------------------------------ pass 1b
// Parallel deterministic reduction: one (batch,row) per block.
__global__ __launch_bounds__(256) void reduce_kernel() {
    const int b   = blockIdx.x >> 6;
    const int r   = blockIdx.x & 63;
    const int col = threadIdx.x & 63;
    const int sub = threadIdx.x >> 6;          // 0..3
    __shared__ float sAcc[4][kC];

    constexpr int kPer = kBPB / 4;             // 74 partials per sub
    const int j0 = sub * kPer;
    float s0 = 0.f, s1 = 0.f;
#pragma unroll 2
    for (int i = 0; i < kPer; i += 2) {
        s0 += g_part[b + 2 * (j0 + i)][r][col];
        s1 += g_part[b + 2 * (j0 + i + 1)][r][col];
    }
    sAcc[sub][col] = s0 + s1;
    __syncthreads();
    if (sub == 0)
        g_xcov[b][r][col] = (sAcc[0][col] + sAcc[1][col]) +
                            (sAcc[2][col] + sAcc[3][col]);
}

// ------------------------------------------------------------------ pass 2
// attn v2: 512 threads, dynamic smem (Xc + double-buffered W + T),
// register-prefetched weights so no phase stalls on DRAM.
__global__ __launch_bounds__(512) void attn_kernel(
    const float* __restrict__ Wq, const float* __restrict__ Wk,
    const float* __restrict__ Wv, const float* __restrict__ Wp,
    const float* __restrict__ rescale)
{
    extern __shared__ float dsm[];
    float* sXc = dsm;                    // [64][65]
    float* sW0 = dsm + kC * kPA;         // [64][65]
    float* sW1 = dsm + 2 * kC * kPA;     // [64][65]
    float* sT  = dsm + 3 * kC * kPA;     // [64][65]
    __shared__ float sAttn[kC][16];
    __shared__ float sPart[8][kC];
    __shared__ float sSq[kC], sSk[kC];

    const int b = blockIdx.x, tid = threadIdx.x;
    const int m = tid & 63, oct = tid >> 6;     // oct 0..7, 8 rows/thread

    // --- load Xc (symmetrized) + Wq --------------------------------------
    for (int idx = tid; idx < kC * kC; idx += 512) {
        const int r = idx >> 6, c = idx & 63;
        sXc[r * kPA + c] = g_xcov[b][r][c] + g_xcov[b][c][r];
        sW0[r * kPA + c] = Wq[idx];
    }
    __syncthreads();                                            // A

    // --- Tq = Wq * Xc ; prefetch Wk -> regs -> sW1 ------------------------
    {
        float wreg[8];
#pragma unroll
        for (int t = 0; t < 8; t++) wreg[t] = __ldg(&Wk[((oct + 8 * t) << 6) + m]);
        float acc[8];
#pragma unroll
        for (int t = 0; t < 8; t++) acc[t] = 0.f;
#pragma unroll 8
        for (int j = 0; j < 64; j++) {
            const float xv = sXc[j * kPA + m];
#pragma unroll
            for (int t = 0; t < 8; t++) acc[t] += sW0[(oct + 8 * t) * kPA + j] * xv;
        }
#pragma unroll
        for (int t = 0; t < 8; t++) {
            sT[(oct + 8 * t) * kPA + m] = acc[t];
            sW1[(oct + 8 * t) * kPA + m] = wreg[t];
        }
    }
    __syncthreads();                                            // B

    // --- normq partials + logits ; prefetch Wv -> regs --------------------
    float wvreg[8];
#pragma unroll
    for (int t = 0; t < 8; t++) wvreg[t] = __ldg(&Wv[((oct + 8 * t) << 6) + m]);
    {
        float s = 0.f;
#pragma unroll
        for (int jj = 0; jj < 8; jj++) {
            const int j = oct * 8 + jj;
            s += sT[m * kPA + j] * sW0[m * kPA + j];
        }
        sPart[oct][m] = s;
    }
    for (int idx = tid; idx < 1024; idx += 512) {   // G[kc][e]=dot(Wk[kc],Tq[qc])
        const int h = idx >> 8, d = (idx >> 4) & 15, e = idx & 15;
        const int kc = (h << 4) + d, qc = (h << 4) + e;
        float s = 0.f;
#pragma unroll 8
        for (int mm = 0; mm < 64; mm++)
            s += sW1[kc * kPA + mm] * sT[qc * kPA + mm];
        sAttn[kc][e] = s;
    }
    __syncthreads();                                            // C
    if (tid < 64) {
        float s = 0.f;
#pragma unroll
        for (int q = 0; q < 8; q++) s += sPart[q][tid];
        sSq[tid] = fmaxf(sqrtf(fmaxf(s, 0.f)), 1e-12f);
    }

    // --- Tk = Wk * Xc ; stage Wv -> sW0 -----------------------------------
    {
        float acc[8];
#pragma unroll
        for (int t = 0; t < 8; t++) acc[t] = 0.f;
#pragma unroll 8
        for (int j = 0; j < 64; j++) {
            const float xv = sXc[j * kPA + m];
#pragma unroll
            for (int t = 0; t < 8; t++) acc[t] += sW1[(oct + 8 * t) * kPA + j] * xv;
        }
#pragma unroll
        for (int t = 0; t < 8; t++) {
            sT[(oct + 8 * t) * kPA + m] = acc[t];
            sW0[(oct + 8 * t) * kPA + m] = wvreg[t];
        }
    }
    __syncthreads();                                            // D

    // --- normk partials ; prefetch Wp -> regs -----------------------------
    float wpreg[8];
#pragma unroll
    for (int t = 0; t < 8; t++) wpreg[t] = __ldg(&Wp[((oct + 8 * t) << 6) + m]);
    {
        float s = 0.f;
#pragma unroll
        for (int jj = 0; jj < 8; jj++) {
            const int j = oct * 8 + jj;
            s += sT[m * kPA + j] * sW1[m * kPA + j];
        }
        sPart[oct][m] = s;
    }
    __syncthreads();                                            // E

    // --- combine normk + softmax (tid<64) ; stage Wp -> sW1 ---------------
    if (tid < 64) {
        float s = 0.f;
#pragma unroll
        for (int q = 0; q < 8; q++) s += sPart[q][tid];
        const float nk = fmaxf(sqrtf(fmaxf(s, 0.f)), 1e-12f);
        const int kc = tid, h = kc >> 4;
        const float rs = __ldg(&rescale[h]);
        const float invk = 1.f / nk;
        float logit[16], mx = -1e30f;
#pragma unroll
        for (int e = 0; e < 16; e++) {
            logit[e] = sAttn[kc][e] * invk / sSq[(kc & 48) + e] * rs;
            mx = fmaxf(mx, logit[e]);
        }
        float sum = 0.f;
#pragma unroll
        for (int e = 0; e < 16; e++) { logit[e] = expf(logit[e] - mx); sum += logit[e]; }
        const float inv = 1.f / sum;
#pragma unroll
        for (int e = 0; e < 16; e++) sAttn[kc][e] = logit[e] * inv;
    }
#pragma unroll
    for (int t = 0; t < 8; t++)
        sW1[(oct + 8 * t) * kPA + m] = wpreg[t];
    __syncthreads();                                            // F

    // --- R = A_blockdiag * Wv -> sT ---------------------------------------
    for (int idx = tid; idx < kC * kC; idx += 512) {
        const int r = idx >> 6, cc = idx & 63, h = r >> 4;
        float s = 0.f;
#pragma unroll
        for (int e = 0; e < 16; e++)
            s += sAttn[r][e] * sW0[((h << 4) + e) * kPA + cc];
        sT[r * kPA + cc] = s;
    }
    __syncthreads();                                            // G

    // --- M = Wp * R -> bf16 ------------------------------------------------
    {
        float acc[8];
#pragma unroll
        for (int t = 0; t < 8; t++) acc[t] = 0.f;
#pragma unroll 8
        for (int j = 0; j < 64; j++) {
            const float xv = sT[j * kPA + m];
#pragma unroll
            for (int t = 0; t < 8; t++) acc[t] += sW1[(oct + 8 * t) * kPA + j] * xv;
        }
#pragma unroll
        for (int t = 0; t < 8; t++)
            g_M[b][oct + 8 * t][m] = __float2bfloat16(acc[t]);
    }
}

// ------------------------------------------------------------------ pass 3
// out = x + M x + bp. Two 64x128 chunks per block, register double-buffered.
__global__ __launch_bounds__(256) void apply_kernel(
    const float* __restrict__ x, const float* __restrict__ bp,
    float* __restrict__ out)
{
    __shared__ float sXf[kC][kPF];
    __shared__ __nv_bfloat16 sM[kC][kPM];

    const int tid = threadIdx.x;
    const int warp = tid >> 5, lane = tid & 31;
    const int g = lane >> 2, t2 = (lane & 3) << 1;
    const int gid = blockIdx.x;
    const int b = gid >> 10;                 // 1024 block-slots per batch
    const int c0idx = gid & 1023;            // handles chunks c0idx, c0idx+1024
    const float* xb = x + (size_t)b * kC * kN;
    float* ob = out + (size_t)b * kC * kN;

    for (int idx = tid; idx < kC * kC; idx += 256)
        sM[idx >> 6][idx & 63] = g_M[b][idx >> 6][idx & 63];

    float4 buf[8];
    {
        const int col0 = c0idx * kChunk;
#pragma unroll
        for (int i = 0; i < 8; i++) {
            const int idx4 = tid + (i << 8);
            buf[i] = *reinterpret_cast<const float4*>(
                xb + (size_t)(idx4 >> 5) * kN + col0 + ((idx4 & 31) << 2));
        }
    }

#pragma unroll
    for (int it = 0; it < 2; it++) {
        const int col0 = (c0idx + (it << 10)) * kChunk;
        if (it) __syncthreads();             // epilogue reads of prev tile done
#pragma unroll
        for (int i = 0; i < 8; i++) {
            const int idx4 = tid + (i << 8);
            *reinterpret_cast<float4*>(&sXf[idx4 >> 5][(idx4 & 31) << 2]) = buf[i];
        }
        __syncthreads();

        if (it == 0) {                        // prefetch second chunk
            const int ncol0 = (c0idx + 1024) * kChunk;
#pragma unroll
            for (int i = 0; i < 8; i++) {
                const int idx4 = tid + (i << 8);
                buf[i] = *reinterpret_cast<const float4*>(
                    xb + (size_t)(idx4 >> 5) * kN + ncol0 + ((idx4 & 31) << 2));
            }
        }

        float acc[2][4][4];
#pragma unroll
        for (int s = 0; s < 2; s++)
#pragma unroll
            for (int ot = 0; ot < 4; ot++)
#pragma unroll
                for (int r = 0; r < 4; r++) acc[s][ot][r] = 0.f;

        uint32_t bfrag[2][4][2];
#pragma unroll
        for (int s = 0; s < 2; s++) {
            const int colb = ((warp + (s << 3)) << 3) + g;
#pragma unroll
            for (int ks = 0; ks < 4; ks++) {
                const int kc = (ks << 4) + t2;
                bfrag[s][ks][0] = pack_bf16x2(sXf[kc][colb],     sXf[kc + 1][colb]);
                bfrag[s][ks][1] = pack_bf16x2(sXf[kc + 8][colb], sXf[kc + 9][colb]);
            }
        }

#pragma unroll
        for (int ot = 0; ot < 4; ot++) {
#pragma unroll
            for (int ks = 0; ks < 4; ks++) {
                uint32_t a[4];
                const int ra = (ot << 4) + g, ca = (ks << 4) + t2;
                a[0] = ld_u32_bf(&sM[ra][ca]);     a[1] = ld_u32_bf(&sM[ra + 8][ca]);
                a[2] = ld_u32_bf(&sM[ra][ca + 8]); a[3] = ld_u32_bf(&sM[ra + 8][ca + 8]);
                mma_bf16(acc[0][ot], a, bfrag[0][ks]);
                mma_bf16(acc[1][ot], a, bfrag[1][ks]);
            }
        }

#pragma unroll
        for (int s = 0; s < 2; s++) {
            const int c0 = ((warp + (s << 3)) << 3) + t2;
#pragma unroll
            for (int ot = 0; ot < 4; ot++) {
                const int r0 = (ot << 4) + g;
                const float bp0 = __ldg(&bp[r0]), bp1 = __ldg(&bp[r0 + 8]);
                float2 v0, v1;
                v0.x = acc[s][ot][0] + sXf[r0][c0]         + bp0;
                v0.y = acc[s][ot][1] + sXf[r0][c0 + 1]     + bp0;
                v1.x = acc[s][ot][2] + sXf[r0 + 8][c0]     + bp1;
                v1.y = acc[s][ot][3] + sXf[r0 + 8][c0 + 1] + bp1;
                *reinterpret_cast<float2*>(&ob[(size_t)r0 * kN + col0 + c0]) = v0;
                *reinterpret_cast<float2*>(&ob[(size_t)(r0 + 8) * kN + col0 + c0]) = v1;
            }
        }
    }
}

// ------------------------------------------------------------------ launch
extern "C" void kernel_launch(void* const* d_in, const int* in_sizes, int n_in,
                              void* d_out, int out_size) {
    const float* x       = (const float*)d_in[0];
    const float* Wq      = (const float*)d_in[1];
    const float* Wk      = (const float*)d_in[2];
    const float* Wv      = (const float*)d_in[3];
    const float* Wp      = (const float*)d_in[4];
    const float* bp      = (const float*)d_in[5];
    const float* rescale = (const float*)d_in[6];
    float* out           = (float*)d_out;

    cudaFuncSetAttribute(attn_kernel,
                         cudaFuncAttributeMaxDynamicSharedMemorySize, kAttnSmem);

    syrk_kernel<<<kGrid1, 256>>>(x);
    reduce_kernel<<<2 * kC, 256>>>();
    attn_kernel<<<2, 512, kAttnSmem>>>(Wq, Wk, Wv, Wp, rescale);
    apply_kernel<<<2048, 256>>>(x, bp, out);
}

// round 10
// speedup vs baseline: 2.3961x; 1.0902x over previous
#include <cuda_runtime.h>
#include <cuda_bf16.h>
#include <stdint.h>
#include <stddef.h>

namespace {
constexpr int kC       = 64;
constexpr int kN       = 512 * 512;     // 262144
constexpr int kChunk   = 128;
constexpr int kNChunks = kN / kChunk;   // 2048
constexpr int kGrid1   = 592;           // syrk blocks (even: 2 batches interleaved)
constexpr int kBPB     = kGrid1 / 2;    // 296 blocks per batch
constexpr int kP1      = 136;           // bf16 smem pitch (conflict-free)
constexpr int kPF      = 132;           // f32 smem pitch
constexpr int kPM      = 72;            // bf16 M pitch (conflict-free)
constexpr int kPA      = 65;            // attn f32 pitch
constexpr int kAttnSmem  = 4 * kC * kPA * 4;                 // Xc, W0, W1, T
constexpr int kApplySmem = kC * kPM * 2 + 2 * kC * kPF * 4;  // sM + 2 stages
}

__device__ float g_part[kGrid1][kC][kC];     // per-block U = 0.5*HH^T + HL^T
__device__ float g_xcov[2][kC][kC];          // summed U (Xc = U + U^T at use)
__device__ __nv_bfloat16 g_M[2][kC][kC];

__device__ __forceinline__ void mma_bf16(float c[4], const uint32_t a[4],
                                         const uint32_t b[2]) {
    asm volatile(
        "mma.sync.aligned.m16n8k16.row.col.f32.bf16.bf16.f32 "
        "{%0,%1,%2,%3}, {%4,%5,%6,%7}, {%8,%9}, {%0,%1,%2,%3};\n"
        : "+f"(c[0]), "+f"(c[1]), "+f"(c[2]), "+f"(c[3])
        : "r"(a[0]), "r"(a[1]), "r"(a[2]), "r"(a[3]), "r"(b[0]), "r"(b[1]));
}

__device__ __forceinline__ uint32_t ld_u32_bf(const __nv_bfloat16* p) {
    return *reinterpret_cast<const uint32_t*>(p);
}

__device__ __forceinline__ uint32_t pack_bf16x2(float lo, float hi) {
    __nv_bfloat162 h = __floats2bfloat162_rn(lo, hi);
    return *reinterpret_cast<uint32_t*>(&h);
}

__device__ __forceinline__ void cp_async16(float* smem_dst, const float* gmem_src) {
    uint32_t s = (uint32_t)__cvta_generic_to_shared(smem_dst);
    asm volatile("cp.async.cg.shared.global [%0], [%1], 16;\n"
                 :: "r"(s), "l"(gmem_src));
}
__device__ __forceinline__ void cp_async_commit() {
    asm volatile("cp.async.commit_group;\n");
}
template <int N>
__device__ __forceinline__ void cp_async_wait() {
    asm volatile("cp.async.wait_group %0;\n" :: "n"(N));
}

// ------------------------------------------------------------------ pass 1
// U partials: U = 0.5*H H^T + H L^T  (Xcov = sum(U + U^T); LL^T dropped)
__global__ __launch_bounds__(256, 2) void syrk_kernel(const float* __restrict__ x) {
    __shared__ __nv_bfloat16 sH[kC][kP1];
    __shared__ __nv_bfloat16 sL[kC][kP1];

    const int tid = threadIdx.x;
    const int warp = tid >> 5, lane = tid & 31;
    const int g = lane >> 2, t2 = (lane & 3) << 1;
    const int b = blockIdx.x & 1;
    const float* xb = x + (size_t)b * kC * kN;
    const int i0 = warp >> 2, j0 = warp & 3;   // C tile coords

    float accS[2][2][4];   // H H^T
    float accX[2][2][4];   // H L^T
#pragma unroll
    for (int s = 0; s < 2; s++)
#pragma unroll
        for (int n = 0; n < 2; n++)
#pragma unroll
            for (int r = 0; r < 4; r++) { accS[s][n][r] = 0.f; accX[s][n][r] = 0.f; }

    float4 buf[8];
    int c = blockIdx.x >> 1;
    if (c < kNChunks) {
        const int col0 = c * kChunk;
#pragma unroll
        for (int i = 0; i < 8; i++) {
            const int idx4 = tid + (i << 8);
            buf[i] = *reinterpret_cast<const float4*>(
                xb + (size_t)(idx4 >> 5) * kN + col0 + ((idx4 & 31) << 2));
        }
    }

    for (; c < kNChunks; c += kBPB) {
#pragma unroll
        for (int i = 0; i < 8; i++) {
            const int idx4 = tid + (i << 8);
            const int ch = idx4 >> 5, cc = (idx4 & 31) << 2;
            float v[4] = {buf[i].x, buf[i].y, buf[i].z, buf[i].w};
            __nv_bfloat16 h[4], l[4];
#pragma unroll
            for (int k = 0; k < 4; k++) {
                h[k] = __float2bfloat16(v[k]);
                l[k] = __float2bfloat16(v[k] - __bfloat162float(h[k]));
            }
            *reinterpret_cast<__nv_bfloat162*>(&sH[ch][cc])     = __halves2bfloat162(h[0], h[1]);
            *reinterpret_cast<__nv_bfloat162*>(&sH[ch][cc + 2]) = __halves2bfloat162(h[2], h[3]);
            *reinterpret_cast<__nv_bfloat162*>(&sL[ch][cc])     = __halves2bfloat162(l[0], l[1]);
            *reinterpret_cast<__nv_bfloat162*>(&sL[ch][cc + 2]) = __halves2bfloat162(l[2], l[3]);
        }
        __syncthreads();

        const int nc = c + kBPB;                 // prefetch next chunk
        if (nc < kNChunks) {
            const int col0 = nc * kChunk;
#pragma unroll
            for (int i = 0; i < 8; i++) {
                const int idx4 = tid + (i << 8);
                buf[i] = *reinterpret_cast<const float4*>(
                    xb + (size_t)(idx4 >> 5) * kN + col0 + ((idx4 & 31) << 2));
            }
        }

#pragma unroll
        for (int ks = 0; ks < 8; ks++) {
            const int kc = (ks << 4) + t2;
#pragma unroll
            for (int s = 0; s < 2; s++) {
                const int ra = ((i0 + (s << 1)) << 4) + g;
                uint32_t aH[4];
                aH[0] = ld_u32_bf(&sH[ra][kc]);     aH[1] = ld_u32_bf(&sH[ra + 8][kc]);
                aH[2] = ld_u32_bf(&sH[ra][kc + 8]); aH[3] = ld_u32_bf(&sH[ra + 8][kc + 8]);
#pragma unroll
                for (int nh = 0; nh < 2; nh++) {
                    const int rb = (j0 << 4) + (nh << 3) + g;
                    uint32_t bH[2], bL[2];
                    bH[0] = ld_u32_bf(&sH[rb][kc]); bH[1] = ld_u32_bf(&sH[rb][kc + 8]);
                    bL[0] = ld_u32_bf(&sL[rb][kc]); bL[1] = ld_u32_bf(&sL[rb][kc + 8]);
                    mma_bf16(accS[s][nh], aH, bH);
                    mma_bf16(accX[s][nh], aH, bL);
                }
            }
        }
        __syncthreads();
    }

#pragma unroll
    for (int s = 0; s < 2; s++) {
        const int r0 = ((i0 + (s << 1)) << 4) + g;
#pragma unroll
        for (int nh = 0; nh < 2; nh++) {
            const int cb = (j0 << 4) + (nh << 3) + t2;
            g_part[blockIdx.x][r0][cb]         = 0.5f * accS[s][nh][0] + accX[s][nh][0];
            g_part[blockIdx.x][r0][cb + 1]     = 0.5f * accS[s][nh][1] + accX[s][nh][1];
            g_part[blockIdx.x][r0 + 8][cb]     = 0.5f * accS[s][nh][2] + accX[s][nh][2];
            g_part[blockIdx.x][r0 + 8][cb + 1] = 0.5f * accS[s][nh][3] + accX[s][nh][3];
        }
    }
}

// ------------------------------------------------------------------ pass 1b
// Parallel deterministic reduction: one (batch,row) per block.
__global__ __launch_bounds__(256) void reduce_kernel() {
    const int b   = blockIdx.x >> 6;
    const int r   = blockIdx.x & 63;
    const int col = threadIdx.x & 63;
    const int sub = threadIdx.x >> 6;          // 0..3
    __shared__ float sAcc[4][kC];

    constexpr int kPer = kBPB / 4;             // 74 partials per sub
    const int j0 = sub * kPer;
    float s0 = 0.f, s1 = 0.f;
#pragma unroll 2
    for (int i = 0; i < kPer; i += 2) {
        s0 += g_part[b + 2 * (j0 + i)][r][col];
        s1 += g_part[b + 2 * (j0 + i + 1)][r][col];
    }
    sAcc[sub][col] = s0 + s1;
    __syncthreads();
    if (sub == 0)
        g_xcov[b][r][col] = (sAcc[0][col] + sAcc[1][col]) +
                            (sAcc[2][col] + sAcc[3][col]);
}

// ------------------------------------------------------------------ pass 2
// attn v2: 512 threads, dynamic smem, register-prefetched weights.
__global__ __launch_bounds__(512) void attn_kernel(
    const float* __restrict__ Wq, const float* __restrict__ Wk,
    const float* __restrict__ Wv, const float* __restrict__ Wp,
    const float* __restrict__ rescale)
{
    extern __shared__ float dsm[];
    float* sXc = dsm;                    // [64][65]
    float* sW0 = dsm + kC * kPA;         // [64][65]
    float* sW1 = dsm + 2 * kC * kPA;     // [64][65]
    float* sT  = dsm + 3 * kC * kPA;     // [64][65]
    __shared__ float sAttn[kC][16];
    __shared__ float sPart[8][kC];
    __shared__ float sSq[kC], sSk[kC];

    const int b = blockIdx.x, tid = threadIdx.x;
    const int m = tid & 63, oct = tid >> 6;     // oct 0..7, 8 rows/thread

    for (int idx = tid; idx < kC * kC; idx += 512) {
        const int r = idx >> 6, c = idx & 63;
        sXc[r * kPA + c] = g_xcov[b][r][c] + g_xcov[b][c][r];
        sW0[r * kPA + c] = Wq[idx];
    }
    __syncthreads();                                            // A

    {
        float wreg[8];
#pragma unroll
        for (int t = 0; t < 8; t++) wreg[t] = __ldg(&Wk[((oct + 8 * t) << 6) + m]);
        float acc[8];
#pragma unroll
        for (int t = 0; t < 8; t++) acc[t] = 0.f;
#pragma unroll 8
        for (int j = 0; j < 64; j++) {
            const float xv = sXc[j * kPA + m];
#pragma unroll
            for (int t = 0; t < 8; t++) acc[t] += sW0[(oct + 8 * t) * kPA + j] * xv;
        }
#pragma unroll
        for (int t = 0; t < 8; t++) {
            sT[(oct + 8 * t) * kPA + m] = acc[t];
            sW1[(oct + 8 * t) * kPA + m] = wreg[t];
        }
    }
    __syncthreads();                                            // B

    float wvreg[8];
#pragma unroll
    for (int t = 0; t < 8; t++) wvreg[t] = __ldg(&Wv[((oct + 8 * t) << 6) + m]);
    {
        float s = 0.f;
#pragma unroll
        for (int jj = 0; jj < 8; jj++) {
            const int j = oct * 8 + jj;
            s += sT[m * kPA + j] * sW0[m * kPA + j];
        }
        sPart[oct][m] = s;
    }
    for (int idx = tid; idx < 1024; idx += 512) {
        const int h = idx >> 8, d = (idx >> 4) & 15, e = idx & 15;
        const int kc = (h << 4) + d, qc = (h << 4) + e;
        float s = 0.f;
#pragma unroll 8
        for (int mm = 0; mm < 64; mm++)
            s += sW1[kc * kPA + mm] * sT[qc * kPA + mm];
        sAttn[kc][e] = s;
    }
    __syncthreads();                                            // C
    if (tid < 64) {
        float s = 0.f;
#pragma unroll
        for (int q = 0; q < 8; q++) s += sPart[q][tid];
        sSq[tid] = fmaxf(sqrtf(fmaxf(s, 0.f)), 1e-12f);
    }

    {
        float acc[8];
#pragma unroll
        for (int t = 0; t < 8; t++) acc[t] = 0.f;
#pragma unroll 8
        for (int j = 0; j < 64; j++) {
            const float xv = sXc[j * kPA + m];
#pragma unroll
            for (int t = 0; t < 8; t++) acc[t] += sW1[(oct + 8 * t) * kPA + j] * xv;
        }
#pragma unroll
        for (int t = 0; t < 8; t++) {
            sT[(oct + 8 * t) * kPA + m] = acc[t];
            sW0[(oct + 8 * t) * kPA + m] = wvreg[t];
        }
    }
    __syncthreads();                                            // D

    float wpreg[8];
#pragma unroll
    for (int t = 0; t < 8; t++) wpreg[t] = __ldg(&Wp[((oct + 8 * t) << 6) + m]);
    {
        float s = 0.f;
#pragma unroll
        for (int jj = 0; jj < 8; jj++) {
            const int j = oct * 8 + jj;
            s += sT[m * kPA + j] * sW1[m * kPA + j];
        }
        sPart[oct][m] = s;
    }
    __syncthreads();                                            // E

    if (tid < 64) {
        float s = 0.f;
#pragma unroll
        for (int q = 0; q < 8; q++) s += sPart[q][tid];
        const float nk = fmaxf(sqrtf(fmaxf(s, 0.f)), 1e-12f);
        const int kc = tid, h = kc >> 4;
        const float rs = __ldg(&rescale[h]);
        const float invk = 1.f / nk;
        float logit[16], mx = -1e30f;
#pragma unroll
        for (int e = 0; e < 16; e++) {
            logit[e] = sAttn[kc][e] * invk / sSq[(kc & 48) + e] * rs;
            mx = fmaxf(mx, logit[e]);
        }
        float sum = 0.f;
#pragma unroll
        for (int e = 0; e < 16; e++) { logit[e] = expf(logit[e] - mx); sum += logit[e]; }
        const float inv = 1.f / sum;
#pragma unroll
        for (int e = 0; e < 16; e++) sAttn[kc][e] = logit[e] * inv;
    }
#pragma unroll
    for (int t = 0; t < 8; t++)
        sW1[(oct + 8 * t) * kPA + m] = wpreg[t];
    __syncthreads();                                            // F

    for (int idx = tid; idx < kC * kC; idx += 512) {
        const int r = idx >> 6, cc = idx & 63, h = r >> 4;
        float s = 0.f;
#pragma unroll
        for (int e = 0; e < 16; e++)
            s += sAttn[r][e] * sW0[((h << 4) + e) * kPA + cc];
        sT[r * kPA + cc] = s;
    }
    __syncthreads();                                            // G

    {
        float acc[8];
#pragma unroll
        for (int t = 0; t < 8; t++) acc[t] = 0.f;
#pragma unroll 8
        for (int j = 0; j < 64; j++) {
            const float xv = sT[j * kPA + m];
#pragma unroll
            for (int t = 0; t < 8; t++) acc[t] += sW1[(oct + 8 * t) * kPA + j] * xv;
        }
#pragma unroll
        for (int t = 0; t < 8; t++)
            g_M[b][oct + 8 * t][m] = __float2bfloat16(acc[t]);
    }
}

// ------------------------------------------------------------------ pass 3
// out = x + M x + bp. 4 chunks/block, cp.async 2-stage smem pipeline.
__global__ __launch_bounds__(256, 3) void apply_kernel(
    const float* __restrict__ x, const float* __restrict__ bp,
    float* __restrict__ out)
{
    extern __shared__ char dsm2[];
    __nv_bfloat16* sM = reinterpret_cast<__nv_bfloat16*>(dsm2);      // [64][72]
    float* sX0 = reinterpret_cast<float*>(dsm2 + kC * kPM * 2);      // [64][132]
    float* sX1 = sX0 + kC * kPF;

    const int tid = threadIdx.x;
    const int warp = tid >> 5, lane = tid & 31;
    const int g = lane >> 2, t2 = (lane & 3) << 1;
    const int gid = blockIdx.x;
    const int b = gid >> 9;                  // 512 block-slots per batch
    const int c0idx = gid & 511;             // chunks c0idx + k*512, k=0..3
    const float* xb = x + (size_t)b * kC * kN;
    float* ob = out + (size_t)b * kC * kN;

    for (int idx = tid; idx < kC * kC; idx += 256)
        sM[(idx >> 6) * kPM + (idx & 63)] = g_M[b][idx >> 6][idx & 63];

    // hoist bias (thread's epilogue rows are fixed across chunks)
    float bpv[4][2];
#pragma unroll
    for (int ot = 0; ot < 4; ot++) {
        bpv[ot][0] = __ldg(&bp[(ot << 4) + g]);
        bpv[ot][1] = __ldg(&bp[(ot << 4) + g + 8]);
    }

    const int ch8 = tid >> 5, c48 = (lane << 2);   // this thread's copy slice

    // issue stage 0
    {
        const int col0 = c0idx * kChunk;
#pragma unroll
        for (int i = 0; i < 8; i++) {
            const int ch = ch8 + (i << 3);
            cp_async16(sX0 + ch * kPF + c48,
                       xb + (size_t)ch * kN + col0 + c48);
        }
        cp_async_commit();
    }

#pragma unroll
    for (int k = 0; k < 4; k++) {
        const int col0 = (c0idx + (k << 9)) * kChunk;
        float* sXp = (k & 1) ? sX1 : sX0;

        if (k + 1 < 4) {                     // issue next stage
            const int ncol0 = (c0idx + ((k + 1) << 9)) * kChunk;
            float* sXn = ((k + 1) & 1) ? sX1 : sX0;
#pragma unroll
            for (int i = 0; i < 8; i++) {
                const int ch = ch8 + (i << 3);
                cp_async16(sXn + ch * kPF + c48,
                           xb + (size_t)ch * kN + ncol0 + c48);
            }
            cp_async_commit();
            cp_async_wait<1>();
        } else {
            cp_async_wait<0>();
        }
        __syncthreads();

        float acc[2][4][4];
#pragma unroll
        for (int s = 0; s < 2; s++)
#pragma unroll
            for (int ot = 0; ot < 4; ot++)
#pragma unroll
                for (int r = 0; r < 4; r++) acc[s][ot][r] = 0.f;

        uint32_t bfrag[2][4][2];
#pragma unroll
        for (int s = 0; s < 2; s++) {
            const int colb = ((warp + (s << 3)) << 3) + g;
#pragma unroll
            for (int ks = 0; ks < 4; ks++) {
                const int kc = (ks << 4) + t2;
                bfrag[s][ks][0] = pack_bf16x2(sXp[kc * kPF + colb],
                                              sXp[(kc + 1) * kPF + colb]);
                bfrag[s][ks][1] = pack_bf16x2(sXp[(kc + 8) * kPF + colb],
                                              sXp[(kc + 9) * kPF + colb]);
            }
        }

#pragma unroll
        for (int ot = 0; ot < 4; ot++) {
#pragma unroll
            for (int ks = 0; ks < 4; ks++) {
                uint32_t a[4];
                const int ra = (ot << 4) + g, ca = (ks << 4) + t2;
                a[0] = ld_u32_bf(&sM[ra * kPM + ca]);
                a[1] = ld_u32_bf(&sM[(ra + 8) * kPM + ca]);
                a[2] = ld_u32_bf(&sM[ra * kPM + ca + 8]);
                a[3] = ld_u32_bf(&sM[(ra + 8) * kPM + ca + 8]);
                mma_bf16(acc[0][ot], a, bfrag[0][ks]);
                mma_bf16(acc[1][ot], a, bfrag[1][ks]);
            }
        }

#pragma unroll
        for (int s = 0; s < 2; s++) {
            const int c0 = ((warp + (s << 3)) << 3) + t2;
#pragma unroll
            for (int ot = 0; ot < 4; ot++) {
                const int r0 = (ot << 4) + g;
                float2 v0, v1;
                v0.x = acc[s][ot][0] + sXp[r0 * kPF + c0]           + bpv[ot][0];
                v0.y = acc[s][ot][1] + sXp[r0 * kPF + c0 + 1]       + bpv[ot][0];
                v1.x = acc[s][ot][2] + sXp[(r0 + 8) * kPF + c0]     + bpv[ot][1];
                v1.y = acc[s][ot][3] + sXp[(r0 + 8) * kPF + c0 + 1] + bpv[ot][1];
                *reinterpret_cast<float2*>(&ob[(size_t)r0 * kN + col0 + c0]) = v0;
                *reinterpret_cast<float2*>(&ob[(size_t)(r0 + 8) * kN + col0 + c0]) = v1;
            }
        }
        __syncthreads();   // tile reads done before next cp.async overwrites
    }
}

// ------------------------------------------------------------------ launch
extern "C" void kernel_launch(void* const* d_in, const int* in_sizes, int n_in,
                              void* d_out, int out_size) {
    const float* x       = (const float*)d_in[0];
    const float* Wq      = (const float*)d_in[1];
    const float* Wk      = (const float*)d_in[2];
    const float* Wv      = (const float*)d_in[3];
    const float* Wp      = (const float*)d_in[4];
    const float* bp      = (const float*)d_in[5];
    const float* rescale = (const float*)d_in[6];
    float* out           = (float*)d_out;

    cudaFuncSetAttribute(attn_kernel,
                         cudaFuncAttributeMaxDynamicSharedMemorySize, kAttnSmem);
    cudaFuncSetAttribute(apply_kernel,
                         cudaFuncAttributeMaxDynamicSharedMemorySize, kApplySmem);

    syrk_kernel<<<kGrid1, 256>>>(x);
    reduce_kernel<<<2 * kC, 256>>>();
    attn_kernel<<<2, 512, kAttnSmem>>>(Wq, Wk, Wv, Wp, rescale);
    apply_kernel<<<1024, 256, kApplySmem>>>(x, bp, out);
}